// round 3
// baseline (speedup 1.0000x reference)
#include <cuda_runtime.h>
#include <math.h>

#define NQ   50000
#define KK   48
#define CC   128
#define HH   8
#define DD   16
#define FF_  256
#define OUTC 128

typedef unsigned long long u64;

// packed f32x2 FMA: d += a*b (two independent fp32 FMAs, exact fp32 semantics)
__device__ __forceinline__ void fma2(u64& d, u64 a, u64 b) {
    asm("fma.rn.f32x2 %0, %1, %2, %0;" : "+l"(d) : "l"(a), "l"(b));
}
__device__ __forceinline__ u64 pk2(float a, float b) {
    u64 r; asm("mov.b64 %0,{%1,%2};" : "=l"(r) : "f"(a), "f"(b)); return r;
}
__device__ __forceinline__ float upk_add(u64 v) {
    float x, y; asm("mov.b64 {%0,%1},%2;" : "=f"(x), "=f"(y) : "l"(v));
    return x + y;
}

// Scratch (device globals: allocation-guard-safe)
__device__ float g_QW[(size_t)NQ * 1024];   // [n][h][c]  = sum_d q[hd]*wk[hd][c]
__device__ float g_QB[(size_t)NQ * 8];      // [n][h]     = sum_d q[hd]*bk[hd]
__device__ float g_mix[(size_t)NQ * 1024];  // [n][h][c]  = sum_k attn[h,k]*kf[k,c]

// ---------------------------------------------------------------------------
// Kernel 1: Q = vf @ wq^T + bq, then QW[n,h,c] = sum_d Q[hd]*wk[hd,c], QB.
// 64 queries per 256-thread block. dynamic smem = 64KB.
// ---------------------------------------------------------------------------
__global__ __launch_bounds__(256) void k_qw(const float* __restrict__ vf,
                                            const float* __restrict__ ipw,
                                            const float* __restrict__ ipb) {
    extern __shared__ float sm[];
    float* xs = sm;            // 64*128
    float* qs = sm + 64 * 128; // 64*128
    int q0 = blockIdx.x * 64;
    int tid = threadIdx.x;

    for (int i = tid; i < 64 * 128; i += 256) {
        int qq = i >> 7;
        xs[i] = (q0 + qq < NQ) ? vf[(size_t)(q0 + qq) * CC + (i & 127)] : 0.f;
    }
    __syncthreads();

    int o = tid & 127, g = tid >> 7;
    // ---- Q : two passes of 16 queries to bound register pressure ----
    {
        const float* wq = ipw + (size_t)o * CC;  // wq rows 0..127
        float b = ipb[o];
        for (int half = 0; half < 2; half++) {
            int qbase = g * 32 + half * 16;
            u64 acc[16];
#pragma unroll
            for (int j = 0; j < 16; j++) acc[j] = 0ull;
            for (int cc = 0; cc < CC; cc += 4) {
                ulonglong2 w2 = *(const ulonglong2*)(wq + cc);
#pragma unroll
                for (int j = 0; j < 16; j++) {
                    ulonglong2 x2 = *(const ulonglong2*)(xs + (qbase + j) * CC + cc);
                    fma2(acc[j], w2.x, x2.x);
                    fma2(acc[j], w2.y, x2.y);
                }
            }
#pragma unroll
            for (int j = 0; j < 16; j++) qs[(qbase + j) * CC + o] = upk_add(acc[j]) + b;
        }
    }
    __syncthreads();

    // ---- QW ----
    {
        const int c = o;
        for (int h = 0; h < HH; h++) {
            u64 wp2[8];
#pragma unroll
            for (int d2 = 0; d2 < 8; d2++)
                wp2[d2] = pk2(ipw[(size_t)(CC + h * 16 + 2 * d2) * CC + c],
                              ipw[(size_t)(CC + h * 16 + 2 * d2 + 1) * CC + c]);
            for (int j = 0; j < 32; j++) {
                int qq = g * 32 + j;
                u64 a2 = 0ull;
#pragma unroll
                for (int d4 = 0; d4 < 4; d4++) {
                    ulonglong2 q2 = *(const ulonglong2*)(qs + qq * CC + h * 16 + d4 * 4);
                    fma2(a2, wp2[2 * d4], q2.x);
                    fma2(a2, wp2[2 * d4 + 1], q2.y);
                }
                if (q0 + qq < NQ)
                    g_QW[(size_t)(q0 + qq) * 1024 + h * 128 + c] = upk_add(a2);
            }
        }
    }
    // ---- QB ----
    for (int i = tid; i < 64 * 8; i += 256) {
        int qq = i >> 3, h = i & 7;
        if (q0 + qq < NQ) {
            float a = 0.f;
#pragma unroll
            for (int d = 0; d < 16; d++)
                a += qs[qq * CC + h * 16 + d] * ipb[CC + h * 16 + d];
            g_QB[(size_t)(q0 + qq) * 8 + h] = a;
        }
    }
}

// ---------------------------------------------------------------------------
// Kernel 2: per-query attention (gather + pos_emb + scores + softmax + mix).
// 1 query per 128-thread block.
// ---------------------------------------------------------------------------
__global__ __launch_bounds__(128) void k_attn(const float* __restrict__ vf,
                                              const float* __restrict__ coords,
                                              const int* __restrict__ kidx,
                                              const int* __restrict__ kmask,
                                              const float* __restrict__ kpw,
                                              const float* __restrict__ kpb) {
    __shared__ float kf[KK][CC];
    __shared__ float s_sc[HH][KK];
    __shared__ int s_idx[KK];
    __shared__ int s_msk[KK];
    __shared__ float s_rel[KK][4];
    __shared__ float s_qc[3];

    int n = blockIdx.x;
    int tid = threadIdx.x;
    if (tid < 3) s_qc[tid] = coords[(size_t)n * 3 + tid];
    if (tid < KK) {
        s_idx[tid] = kidx[(size_t)n * KK + tid];
        s_msk[tid] = kmask[(size_t)n * KK + tid];
    }
    __syncthreads();
    if (tid < KK) {
        int id = s_idx[tid];
        s_rel[tid][0] = coords[(size_t)id * 3 + 0] - s_qc[0];
        s_rel[tid][1] = coords[(size_t)id * 3 + 1] - s_qc[1];
        s_rel[tid][2] = coords[(size_t)id * 3 + 2] - s_qc[2];
    }
    float w0 = kpw[tid * 3 + 0], w1 = kpw[tid * 3 + 1], w2 = kpw[tid * 3 + 2];
    float pb = kpb[tid];
    __syncthreads();

    // gather + pos_emb
#pragma unroll 4
    for (int k = 0; k < KK; k++) {
        float pe = s_rel[k][0] * w0 + s_rel[k][1] * w1 + s_rel[k][2] * w2 + pb;
        pe = fmaxf(pe, 0.f);
        kf[k][tid] = vf[(size_t)s_idx[k] * CC + tid] + pe;
    }

    int lane = tid & 31, wp = tid >> 5;
    // score lane mapping: h = lane>>2 (8 heads), cseg = lane&3 (4 x 32 channels)
    int hh = lane >> 2, cseg = lane & 3;
    const float* qwb = g_QW + (size_t)n * 1024 + hh * 128 + cseg * 32;
    ulonglong2 qp[8];
#pragma unroll
    for (int j = 0; j < 8; j++) qp[j] = *(const ulonglong2*)(qwb + j * 4);
    float qb = g_QB[(size_t)n * 8 + hh];
    __syncthreads();

    // scores: warp wp handles keys wp, wp+4, ... (8 heads in parallel lanes)
    for (int k = wp; k < KK; k += 4) {
        u64 acc = 0ull;
        const float* kr = &kf[k][cseg * 32];
#pragma unroll
        for (int j = 0; j < 8; j++) {
            ulonglong2 k2 = *(const ulonglong2*)(kr + j * 4);
            fma2(acc, qp[j].x, k2.x);
            fma2(acc, qp[j].y, k2.y);
        }
        float s = upk_add(acc);
        s += __shfl_xor_sync(0xffffffffu, s, 1);
        s += __shfl_xor_sync(0xffffffffu, s, 2);
        if (cseg == 0) s_sc[hh][k] = (s + qb) * 0.25f;  // 1/sqrt(16)
    }
    __syncthreads();

    // mask + softmax: warp wp handles heads wp and wp+4
    for (int h = wp; h < HH; h += 4) {
        float a = s_sc[h][lane];
        if (s_msk[lane]) a = -1e9f;
        float bsc = -INFINITY;
        if (lane < 16) {
            bsc = s_sc[h][32 + lane];
            if (s_msk[32 + lane]) bsc = -1e9f;
        }
        float m = fmaxf(a, bsc);
#pragma unroll
        for (int off = 16; off; off >>= 1) m = fmaxf(m, __shfl_xor_sync(0xffffffffu, m, off));
        float ea = expf(a - m);
        float eb = (lane < 16) ? expf(bsc - m) : 0.f;
        float s = ea + eb;
#pragma unroll
        for (int off = 16; off; off >>= 1) s += __shfl_xor_sync(0xffffffffu, s, off);
        float inv = 1.f / s;
        s_sc[h][lane] = ea * inv;
        if (lane < 16) s_sc[h][32 + lane] = eb * inv;
    }
    __syncthreads();

    // mix[h][c] = sum_k attn[h,k]*kf[k,c]; warp wp -> heads 2wp, 2wp+1
    int h0 = 2 * wp, h1 = h0 + 1;
    u64 a00 = 0ull, a01 = 0ull, a10 = 0ull, a11 = 0ull;
#pragma unroll 4
    for (int k = 0; k < KK; k++) {
        ulonglong2 k2 = *(const ulonglong2*)(&kf[k][lane * 4]);
        u64 p0 = pk2(s_sc[h0][k], s_sc[h0][k]);
        u64 p1 = pk2(s_sc[h1][k], s_sc[h1][k]);
        fma2(a00, p0, k2.x); fma2(a01, p0, k2.y);
        fma2(a10, p1, k2.x); fma2(a11, p1, k2.y);
    }
    float* mo = g_mix + (size_t)n * 1024;
    ulonglong2 o0; o0.x = a00; o0.y = a01;
    ulonglong2 o1; o1.x = a10; o1.y = a11;
    *(ulonglong2*)(mo + h0 * 128 + lane * 4) = o0;
    *(ulonglong2*)(mo + h1 * 128 + lane * 4) = o1;
}

// ---------------------------------------------------------------------------
// LayerNorm over 128 channels for a 32-query smem tile; one warp per query.
// ---------------------------------------------------------------------------
__device__ __forceinline__ void ln_norm(float* buf, const float* __restrict__ gg,
                                        const float* __restrict__ bb, int lane, int wid) {
    for (int qq = wid; qq < 32; qq += 8) {
        float4 v = *(const float4*)(buf + qq * CC + lane * 4);
        float s = v.x + v.y + v.z + v.w;
        float s2 = v.x * v.x + v.y * v.y + v.z * v.z + v.w * v.w;
#pragma unroll
        for (int off = 16; off; off >>= 1) {
            s += __shfl_xor_sync(0xffffffffu, s, off);
            s2 += __shfl_xor_sync(0xffffffffu, s2, off);
        }
        float mean = s * (1.f / 128.f);
        float var = s2 * (1.f / 128.f) - mean * mean;
        float inv = rsqrtf(var + 1e-5f);
        float4 g4 = *(const float4*)(gg + lane * 4);
        float4 b4 = *(const float4*)(bb + lane * 4);
        v.x = (v.x - mean) * inv * g4.x + b4.x;
        v.y = (v.y - mean) * inv * g4.y + b4.y;
        v.z = (v.z - mean) * inv * g4.z + b4.z;
        v.w = (v.w - mean) * inv * g4.w + b4.w;
        *(float4*)(buf + qq * CC + lane * 4) = v;
    }
}

// ---------------------------------------------------------------------------
// Kernel 3: dense tail. 32 queries per 256-thread block, dyn smem 80KB.
// ---------------------------------------------------------------------------
__global__ __launch_bounds__(256) void k_tail(
    const float* __restrict__ vf, const float* __restrict__ ipw,
    const float* __restrict__ ipb, const float* __restrict__ wo,
    const float* __restrict__ bo, const float* __restrict__ ln1g,
    const float* __restrict__ ln1b, const float* __restrict__ ln2g,
    const float* __restrict__ ln2b, const float* __restrict__ f1w,
    const float* __restrict__ f1b, const float* __restrict__ f2w,
    const float* __restrict__ f2b, const float* __restrict__ outw,
    const float* __restrict__ outb, const float* __restrict__ ln3g,
    const float* __restrict__ ln3b, float* __restrict__ out) {
    extern __shared__ float sm[];
    float* s_a = sm;           // 32*128: mix tile, later pre-LN3 out
    float* s_c = sm + 4096;    // 32*128: ctx, later x2
    float* s_x = sm + 8192;    // 32*128: x1
    float* s_h = sm + 12288;   // 32*256: hidden
    int q0 = blockIdx.x * 32;
    int tid = threadIdx.x;
    int lane = tid & 31, wid = tid >> 5;

    // ---- ctx[qq][h*16+d] = sum_c mix[qq][h][c]*wv[h16+d][c] + bv ----
    {
        int dq = tid & 15, r = tid >> 4;  // r in 0..15
        for (int h = 0; h < HH; h++) {
            __syncthreads();
            for (int i = tid; i < 32 * 128; i += 256) {
                int qq = i >> 7;
                s_a[i] = (q0 + qq < NQ)
                             ? g_mix[(size_t)(q0 + qq) * 1024 + h * 128 + (i & 127)]
                             : 0.f;
            }
            __syncthreads();
            int o = h * 16 + dq;
            const float* wv = ipw + (size_t)(2 * CC + o) * CC;  // wv rows 256..383
            u64 a0 = 0ull, a1 = 0ull;
            for (int cc = 0; cc < CC; cc += 4) {
                ulonglong2 w2 = *(const ulonglong2*)(wv + cc);
                ulonglong2 m0 = *(const ulonglong2*)(s_a + r * CC + cc);
                ulonglong2 m1 = *(const ulonglong2*)(s_a + (r + 16) * CC + cc);
                fma2(a0, w2.x, m0.x); fma2(a0, w2.y, m0.y);
                fma2(a1, w2.x, m1.x); fma2(a1, w2.y, m1.y);
            }
            float bb = ipb[2 * CC + o];
            s_c[r * CC + o] = upk_add(a0) + bb;
            s_c[(r + 16) * CC + o] = upk_add(a1) + bb;
        }
        __syncthreads();
    }

    // ---- attend = ctx @ wo^T + bo ; x1 = vf + attend ----
    {
        int c = tid & 127, g = tid >> 7;
        u64 acc[16];
#pragma unroll
        for (int j = 0; j < 16; j++) acc[j] = 0ull;
        const float* wrow = wo + (size_t)c * CC;
        for (int cc = 0; cc < CC; cc += 4) {
            ulonglong2 w2 = *(const ulonglong2*)(wrow + cc);
#pragma unroll
            for (int j = 0; j < 16; j++) {
                ulonglong2 x2 = *(const ulonglong2*)(s_c + (g * 16 + j) * CC + cc);
                fma2(acc[j], w2.x, x2.x);
                fma2(acc[j], w2.y, x2.y);
            }
        }
        float bb = bo[c];
#pragma unroll
        for (int j = 0; j < 16; j++) {
            int qq = g * 16 + j;
            float vfv = (q0 + qq < NQ) ? vf[(size_t)(q0 + qq) * CC + c] : 0.f;
            s_x[qq * CC + c] = vfv + upk_add(acc[j]) + bb;
        }
        __syncthreads();
    }
    ln_norm(s_x, ln1g, ln1b, lane, wid);
    __syncthreads();

    // ---- hidden = relu(x1 @ ff1^T + b1) : two passes of 16 queries ----
    {
        int f = tid;
        const float* wrow = f1w + (size_t)f * CC;
        float bb = f1b[f];
        for (int half = 0; half < 2; half++) {
            u64 acc[16];
#pragma unroll
            for (int j = 0; j < 16; j++) acc[j] = 0ull;
            for (int cc = 0; cc < CC; cc += 4) {
                ulonglong2 w2 = *(const ulonglong2*)(wrow + cc);
#pragma unroll
                for (int j = 0; j < 16; j++) {
                    ulonglong2 x2 =
                        *(const ulonglong2*)(s_x + (half * 16 + j) * CC + cc);
                    fma2(acc[j], w2.x, x2.x);
                    fma2(acc[j], w2.y, x2.y);
                }
            }
#pragma unroll
            for (int j = 0; j < 16; j++)
                s_h[(half * 16 + j) * FF_ + f] = fmaxf(upk_add(acc[j]) + bb, 0.f);
        }
        __syncthreads();
    }

    // ---- y = hidden @ ff2^T + b2 ; x2 = x1 + y ----
    {
        int c = tid & 127, g = tid >> 7;
        u64 acc[16];
#pragma unroll
        for (int j = 0; j < 16; j++) acc[j] = 0ull;
        const float* wrow = f2w + (size_t)c * FF_;
        for (int ff = 0; ff < FF_; ff += 4) {
            ulonglong2 w2 = *(const ulonglong2*)(wrow + ff);
#pragma unroll
            for (int j = 0; j < 16; j++) {
                ulonglong2 h2 = *(const ulonglong2*)(s_h + (g * 16 + j) * FF_ + ff);
                fma2(acc[j], w2.x, h2.x);
                fma2(acc[j], w2.y, h2.y);
            }
        }
        float bb = f2b[c];
#pragma unroll
        for (int j = 0; j < 16; j++) {
            int qq = g * 16 + j;
            s_c[qq * CC + c] = s_x[qq * CC + c] + upk_add(acc[j]) + bb;
        }
        __syncthreads();
    }
    ln_norm(s_c, ln2g, ln2b, lane, wid);
    __syncthreads();

    // ---- o = x2 @ outw^T + outb ----
    {
        int o = tid & 127, g = tid >> 7;
        u64 acc[16];
#pragma unroll
        for (int j = 0; j < 16; j++) acc[j] = 0ull;
        const float* wrow = outw + (size_t)o * CC;
        for (int cc = 0; cc < CC; cc += 4) {
            ulonglong2 w2 = *(const ulonglong2*)(wrow + cc);
#pragma unroll
            for (int j = 0; j < 16; j++) {
                ulonglong2 x2 = *(const ulonglong2*)(s_c + (g * 16 + j) * CC + cc);
                fma2(acc[j], w2.x, x2.x);
                fma2(acc[j], w2.y, x2.y);
            }
        }
        float bb = outb[o];
#pragma unroll
        for (int j = 0; j < 16; j++) s_a[(g * 16 + j) * CC + o] = upk_add(acc[j]) + bb;
        __syncthreads();
    }

    // ---- LN3 + relu + store ----
    for (int qq = wid; qq < 32; qq += 8) {
        if (q0 + qq >= NQ) continue;
        float4 v = *(const float4*)(s_a + qq * CC + lane * 4);
        float s = v.x + v.y + v.z + v.w;
        float s2 = v.x * v.x + v.y * v.y + v.z * v.z + v.w * v.w;
#pragma unroll
        for (int off = 16; off; off >>= 1) {
            s += __shfl_xor_sync(0xffffffffu, s, off);
            s2 += __shfl_xor_sync(0xffffffffu, s2, off);
        }
        float mean = s * (1.f / 128.f);
        float var = s2 * (1.f / 128.f) - mean * mean;
        float inv = rsqrtf(var + 1e-5f);
        float4 g4 = *(const float4*)(ln3g + lane * 4);
        float4 b4 = *(const float4*)(ln3b + lane * 4);
        v.x = fmaxf((v.x - mean) * inv * g4.x + b4.x, 0.f);
        v.y = fmaxf((v.y - mean) * inv * g4.y + b4.y, 0.f);
        v.z = fmaxf((v.z - mean) * inv * g4.z + b4.z, 0.f);
        v.w = fmaxf((v.w - mean) * inv * g4.w + b4.w, 0.f);
        *(float4*)(out + (size_t)(q0 + qq) * OUTC + lane * 4) = v;
    }
}

// ---------------------------------------------------------------------------
extern "C" void kernel_launch(void* const* d_in, const int* in_sizes, int n_in,
                              void* d_out, int out_size) {
    const float* vf = (const float*)d_in[0];
    const float* coords = (const float*)d_in[1];
    const int* kidx = (const int*)d_in[2];
    const int* kmask = (const int*)d_in[3];
    const float* ipw = (const float*)d_in[4];
    const float* ipb = (const float*)d_in[5];
    const float* wo = (const float*)d_in[6];
    const float* bo = (const float*)d_in[7];
    const float* kpw = (const float*)d_in[8];
    const float* kpb = (const float*)d_in[9];
    const float* ln1g = (const float*)d_in[10];
    const float* ln1b = (const float*)d_in[11];
    const float* ln2g = (const float*)d_in[12];
    const float* ln2b = (const float*)d_in[13];
    const float* f1w = (const float*)d_in[14];
    const float* f1b = (const float*)d_in[15];
    const float* f2w = (const float*)d_in[16];
    const float* f2b = (const float*)d_in[17];
    const float* outw = (const float*)d_in[18];
    const float* outb = (const float*)d_in[19];
    const float* ln3g = (const float*)d_in[20];
    const float* ln3b = (const float*)d_in[21];
    float* out = (float*)d_out;

    cudaFuncSetAttribute(k_qw, cudaFuncAttributeMaxDynamicSharedMemorySize, 65536);
    cudaFuncSetAttribute(k_tail, cudaFuncAttributeMaxDynamicSharedMemorySize, 81920);

    k_qw<<<(NQ + 63) / 64, 256, 65536>>>(vf, ipw, ipb);
    k_attn<<<NQ, 128>>>(vf, coords, kidx, kmask, kpw, kpb);
    k_tail<<<(NQ + 31) / 32, 256, 81920>>>(vf, ipw, ipb, wo, bo, ln1g, ln1b,
                                           ln2g, ln2b, f1w, f1b, f2w, f2b,
                                           outw, outb, ln3g, ln3b, out);
}

// round 9
// speedup vs baseline: 1.2390x; 1.2390x over previous
#include <cuda_runtime.h>
#include <math.h>

#define NQ   50000
#define KK   48
#define CC   128
#define HH   8
#define DD   16
#define FF_  256
#define OUTC 128

// Scratch (device globals: allocation-guard-safe)
__device__ float g_QW[(size_t)NQ * 1024];  // [n][h][c] = sum_d q[hd]*wk[hd][c]
__device__ float g_QB[(size_t)NQ * 8];     // [n][h]    = sum_d q[hd]*bk[hd]
__device__ float g_ctx[(size_t)NQ * CC];   // [n][h*16+d] attention context (+bv)

// ---------------------------------------------------------------------------
// Kernel 1: Q = vf @ wq^T + bq, then QW[n,h,c] = sum_d Q[hd]*wk[hd,c], QB.
// (identical to the 2186us R2 version)
// ---------------------------------------------------------------------------
__global__ __launch_bounds__(256) void k_qw(const float* __restrict__ vf,
                                            const float* __restrict__ ipw,
                                            const float* __restrict__ ipb) {
    extern __shared__ float sm[];
    float* xs = sm;            // 64*128
    float* qs = sm + 64 * 128; // 64*128
    int q0 = blockIdx.x * 64;
    int tid = threadIdx.x;

    for (int i = tid; i < 64 * 128; i += 256) {
        int qq = i >> 7;
        xs[i] = (q0 + qq < NQ) ? vf[(size_t)(q0 + qq) * CC + (i & 127)] : 0.f;
    }
    __syncthreads();

    int o = tid & 127, g = tid >> 7;
    // ---- Q ----
    {
        float acc[32];
#pragma unroll
        for (int j = 0; j < 32; j++) acc[j] = 0.f;
        const float* wq = ipw + (size_t)o * CC;  // wq rows 0..127
        for (int cc = 0; cc < CC; cc += 4) {
            float4 w4 = *(const float4*)(wq + cc);
#pragma unroll
            for (int j = 0; j < 32; j++) {
                float4 x4 = *(const float4*)(xs + (g * 32 + j) * CC + cc);
                acc[j] += w4.x * x4.x + w4.y * x4.y + w4.z * x4.z + w4.w * x4.w;
            }
        }
        float b = ipb[o];
#pragma unroll
        for (int j = 0; j < 32; j++) qs[(g * 32 + j) * CC + o] = acc[j] + b;
    }
    __syncthreads();

    // ---- QW ----
    {
        const int c = o;
        for (int h = 0; h < HH; h++) {
            float wreg[16];
#pragma unroll
            for (int d = 0; d < 16; d++)
                wreg[d] = ipw[(size_t)(CC + h * 16 + d) * CC + c];  // wk rows 128..255
            for (int j = 0; j < 32; j++) {
                int qq = g * 32 + j;
                float a = 0.f;
#pragma unroll
                for (int d4 = 0; d4 < 16; d4 += 4) {
                    float4 q4 = *(const float4*)(qs + qq * CC + h * 16 + d4);
                    a += q4.x * wreg[d4] + q4.y * wreg[d4 + 1] +
                         q4.z * wreg[d4 + 2] + q4.w * wreg[d4 + 3];
                }
                if (q0 + qq < NQ) g_QW[(size_t)(q0 + qq) * 1024 + h * 128 + c] = a;
            }
        }
    }
    // ---- QB ----
    for (int i = tid; i < 64 * 8; i += 256) {
        int qq = i >> 3, h = i & 7;
        if (q0 + qq < NQ) {
            float a = 0.f;
#pragma unroll
            for (int d = 0; d < 16; d++)
                a += qs[qq * CC + h * 16 + d] * ipb[CC + h * 16 + d];
            g_QB[(size_t)(q0 + qq) * 8 + h] = a;
        }
    }
}

// ---------------------------------------------------------------------------
// Kernel 2: per-query attention (gather + pos_emb + scores + softmax + mix
//           + fused wv projection -> g_ctx). 1 query per 128-thread block.
// ---------------------------------------------------------------------------
__global__ __launch_bounds__(128) void k_attn(const float* __restrict__ vf,
                                              const float* __restrict__ coords,
                                              const int* __restrict__ kidx,
                                              const int* __restrict__ kmask,
                                              const float* __restrict__ kpw,
                                              const float* __restrict__ kpb,
                                              const float* __restrict__ ipw,
                                              const float* __restrict__ ipb) {
    __shared__ float kf[KK][CC];
    __shared__ float s_sc[HH][KK];
    __shared__ float s_mix[HH][132];  // pad 132: rows on distinct banks
    __shared__ int s_idx[KK];
    __shared__ int s_msk[KK];
    __shared__ float s_rel[KK][4];
    __shared__ float s_qc[3];

    int n = blockIdx.x;
    int tid = threadIdx.x;
    if (tid < 3) s_qc[tid] = coords[(size_t)n * 3 + tid];
    if (tid < KK) {
        s_idx[tid] = kidx[(size_t)n * KK + tid];
        s_msk[tid] = kmask[(size_t)n * KK + tid];
    }
    __syncthreads();
    if (tid < KK) {
        int id = s_idx[tid];
        s_rel[tid][0] = coords[(size_t)id * 3 + 0] - s_qc[0];
        s_rel[tid][1] = coords[(size_t)id * 3 + 1] - s_qc[1];
        s_rel[tid][2] = coords[(size_t)id * 3 + 2] - s_qc[2];
    }
    float w0 = kpw[tid * 3 + 0], w1 = kpw[tid * 3 + 1], w2 = kpw[tid * 3 + 2];
    float pb = kpb[tid];
    __syncthreads();

    // gather + pos_emb
#pragma unroll 4
    for (int k = 0; k < KK; k++) {
        float pe = s_rel[k][0] * w0 + s_rel[k][1] * w1 + s_rel[k][2] * w2 + pb;
        pe = fmaxf(pe, 0.f);
        kf[k][tid] = vf[(size_t)s_idx[k] * CC + tid] + pe;
    }

    int lane = tid & 31, wp = tid >> 5;
    // score lane mapping: head = lane>>2, channel segment = lane&3 (32 ch each)
    int hh = lane >> 2, cseg = lane & 3;
    const float* qwb = g_QW + (size_t)n * 1024 + hh * 128 + cseg * 32;
    float4 qp[8];
#pragma unroll
    for (int i = 0; i < 8; i++)
        qp[i] = *(const float4*)(qwb + (((i + 2 * cseg) & 7) << 2));
    float qb = g_QB[(size_t)n * 8 + hh];
    __syncthreads();

    // scores: warp wp handles keys wp, wp+4, ... ; 8 heads in parallel lanes.
    // Per-lane 32-ch dot with a cseg-rotated visit order (conflict-free LDS).
    for (int k = wp; k < KK; k += 4) {
        const float* kr = &kf[k][cseg * 32];
        float s = 0.f;
#pragma unroll
        for (int i = 0; i < 8; i++) {
            float4 k4 = *(const float4*)(kr + (((i + 2 * cseg) & 7) << 2));
            s += qp[i].x * k4.x + qp[i].y * k4.y + qp[i].z * k4.z + qp[i].w * k4.w;
        }
        s += __shfl_xor_sync(0xffffffffu, s, 1);
        s += __shfl_xor_sync(0xffffffffu, s, 2);
        if (cseg == 0) s_sc[hh][k] = (s + qb) * 0.25f;  // 1/sqrt(16)
    }
    __syncthreads();

    // mask + softmax: warp wp handles heads wp and wp+4
    for (int h = wp; h < HH; h += 4) {
        float a = s_sc[h][lane];
        if (s_msk[lane]) a = -1e9f;
        float bsc = -INFINITY;
        if (lane < 16) {
            bsc = s_sc[h][32 + lane];
            if (s_msk[32 + lane]) bsc = -1e9f;
        }
        float m = fmaxf(a, bsc);
#pragma unroll
        for (int off = 16; off; off >>= 1) m = fmaxf(m, __shfl_xor_sync(0xffffffffu, m, off));
        float ea = expf(a - m);
        float eb = (lane < 16) ? expf(bsc - m) : 0.f;
        float s = ea + eb;
#pragma unroll
        for (int off = 16; off; off >>= 1) s += __shfl_xor_sync(0xffffffffu, s, off);
        float inv = 1.f / s;
        s_sc[h][lane] = ea * inv;
        if (lane < 16) s_sc[h][32 + lane] = eb * inv;
    }
    __syncthreads();

    // mix[h][c] = sum_k attn[h,k]*kf[k,c]; warp wp -> heads 2wp, 2wp+1
    int h0 = 2 * wp, h1 = h0 + 1;
    float4 a0 = make_float4(0, 0, 0, 0), a1 = make_float4(0, 0, 0, 0);
#pragma unroll 4
    for (int k = 0; k < KK; k++) {
        float4 k4 = *(const float4*)(&kf[k][lane * 4]);
        float t0 = s_sc[h0][k], t1 = s_sc[h1][k];
        a0.x += k4.x * t0; a0.y += k4.y * t0; a0.z += k4.z * t0; a0.w += k4.w * t0;
        a1.x += k4.x * t1; a1.y += k4.y * t1; a1.z += k4.z * t1; a1.w += k4.w * t1;
    }
    *(float4*)(&s_mix[h0][lane * 4]) = a0;
    *(float4*)(&s_mix[h1][lane * 4]) = a1;
    __syncthreads();

    // fused wv projection: ctx[h*16+d] = sum_c mix[h][c]*wv[h16+d][c] + bv
    // thread tid -> h = tid>>4, d = tid&15. wv rows are L1/L2-resident.
    {
        int h = tid >> 4, d = tid & 15;
        int o = h * 16 + d;
        const float* wv = ipw + (size_t)(2 * CC + o) * CC;  // wv rows 256..383
        const float* mr = &s_mix[h][0];
        float acc = 0.f;
#pragma unroll
        for (int cc = 0; cc < CC; cc += 4) {
            float4 w4 = *(const float4*)(wv + cc);
            float4 m4 = *(const float4*)(mr + cc);
            acc += w4.x * m4.x + w4.y * m4.y + w4.z * m4.z + w4.w * m4.w;
        }
        g_ctx[(size_t)n * CC + o] = acc + ipb[2 * CC + o];
    }
}

// ---------------------------------------------------------------------------
// LayerNorm over 128 channels for a 32-query smem tile; one warp per query.
// ---------------------------------------------------------------------------
__device__ __forceinline__ void ln_norm(float* buf, const float* __restrict__ gg,
                                        const float* __restrict__ bb, int lane, int wid) {
    for (int qq = wid; qq < 32; qq += 8) {
        float4 v = *(const float4*)(buf + qq * CC + lane * 4);
        float s = v.x + v.y + v.z + v.w;
        float s2 = v.x * v.x + v.y * v.y + v.z * v.z + v.w * v.w;
#pragma unroll
        for (int off = 16; off; off >>= 1) {
            s += __shfl_xor_sync(0xffffffffu, s, off);
            s2 += __shfl_xor_sync(0xffffffffu, s2, off);
        }
        float mean = s * (1.f / 128.f);
        float var = s2 * (1.f / 128.f) - mean * mean;
        float inv = rsqrtf(var + 1e-5f);
        float4 g4 = *(const float4*)(gg + lane * 4);
        float4 b4 = *(const float4*)(bb + lane * 4);
        v.x = (v.x - mean) * inv * g4.x + b4.x;
        v.y = (v.y - mean) * inv * g4.y + b4.y;
        v.z = (v.z - mean) * inv * g4.z + b4.z;
        v.w = (v.w - mean) * inv * g4.w + b4.w;
        *(float4*)(buf + qq * CC + lane * 4) = v;
    }
}

// ---------------------------------------------------------------------------
// Kernel 3: dense tail. ctx -> out_proj -> +res LN1 -> FFN -> +res LN2 ->
// head -> LN3 -> relu. 32 queries per 256-thread block, dyn smem 80KB.
// ---------------------------------------------------------------------------
__global__ __launch_bounds__(256) void k_tail(
    const float* __restrict__ vf, const float* __restrict__ wo,
    const float* __restrict__ bo, const float* __restrict__ ln1g,
    const float* __restrict__ ln1b, const float* __restrict__ ln2g,
    const float* __restrict__ ln2b, const float* __restrict__ f1w,
    const float* __restrict__ f1b, const float* __restrict__ f2w,
    const float* __restrict__ f2b, const float* __restrict__ outw,
    const float* __restrict__ outb, const float* __restrict__ ln3g,
    const float* __restrict__ ln3b, float* __restrict__ out) {
    extern __shared__ float sm[];
    float* s_a = sm;           // 32*128: pre-LN3 out
    float* s_c = sm + 4096;    // 32*128: ctx, later x2
    float* s_x = sm + 8192;    // 32*128: x1
    float* s_h = sm + 12288;   // 32*256: hidden
    int q0 = blockIdx.x * 32;
    int tid = threadIdx.x;
    int lane = tid & 31, wid = tid >> 5;

    // ---- load ctx tile ----
    for (int i = tid; i < 32 * 128; i += 256) {
        int qq = i >> 7;
        s_c[i] = (q0 + qq < NQ) ? g_ctx[(size_t)(q0 + qq) * CC + (i & 127)] : 0.f;
    }
    __syncthreads();

    // ---- attend = ctx @ wo^T + bo ; x1 = vf + attend ----
    {
        int c = tid & 127, g = tid >> 7;
        float acc[16];
#pragma unroll
        for (int j = 0; j < 16; j++) acc[j] = 0.f;
        const float* wrow = wo + (size_t)c * CC;
        for (int cc = 0; cc < CC; cc += 4) {
            float4 w4 = *(const float4*)(wrow + cc);
#pragma unroll
            for (int j = 0; j < 16; j++) {
                float4 x4 = *(const float4*)(s_c + (g * 16 + j) * CC + cc);
                acc[j] += w4.x * x4.x + w4.y * x4.y + w4.z * x4.z + w4.w * x4.w;
            }
        }
        float bb = bo[c];
#pragma unroll
        for (int j = 0; j < 16; j++) {
            int qq = g * 16 + j;
            float vfv = (q0 + qq < NQ) ? vf[(size_t)(q0 + qq) * CC + c] : 0.f;
            s_x[qq * CC + c] = vfv + acc[j] + bb;
        }
        __syncthreads();
    }
    ln_norm(s_x, ln1g, ln1b, lane, wid);
    __syncthreads();

    // ---- hidden = relu(x1 @ ff1^T + b1) ----
    {
        int f = tid;
        float acc[32];
#pragma unroll
        for (int j = 0; j < 32; j++) acc[j] = 0.f;
        const float* wrow = f1w + (size_t)f * CC;
        for (int cc = 0; cc < CC; cc += 4) {
            float4 w4 = *(const float4*)(wrow + cc);
#pragma unroll
            for (int j = 0; j < 32; j++) {
                float4 x4 = *(const float4*)(s_x + j * CC + cc);
                acc[j] += w4.x * x4.x + w4.y * x4.y + w4.z * x4.z + w4.w * x4.w;
            }
        }
        float bb = f1b[f];
#pragma unroll
        for (int j = 0; j < 32; j++) s_h[j * FF_ + f] = fmaxf(acc[j] + bb, 0.f);
        __syncthreads();
    }

    // ---- y = hidden @ ff2^T + b2 ; x2 = x1 + y ----
    {
        int c = tid & 127, g = tid >> 7;
        float acc[16];
#pragma unroll
        for (int j = 0; j < 16; j++) acc[j] = 0.f;
        const float* wrow = f2w + (size_t)c * FF_;
        for (int ff = 0; ff < FF_; ff += 4) {
            float4 w4 = *(const float4*)(wrow + ff);
#pragma unroll
            for (int j = 0; j < 16; j++) {
                float4 h4 = *(const float4*)(s_h + (g * 16 + j) * FF_ + ff);
                acc[j] += w4.x * h4.x + w4.y * h4.y + w4.z * h4.z + w4.w * h4.w;
            }
        }
        float bb = f2b[c];
#pragma unroll
        for (int j = 0; j < 16; j++) {
            int qq = g * 16 + j;
            s_c[qq * CC + c] = s_x[qq * CC + c] + acc[j] + bb;
        }
        __syncthreads();
    }
    ln_norm(s_c, ln2g, ln2b, lane, wid);
    __syncthreads();

    // ---- o = x2 @ outw^T + outb ----
    {
        int o = tid & 127, g = tid >> 7;
        float acc[16];
#pragma unroll
        for (int j = 0; j < 16; j++) acc[j] = 0.f;
        const float* wrow = outw + (size_t)o * CC;
        for (int cc = 0; cc < CC; cc += 4) {
            float4 w4 = *(const float4*)(wrow + cc);
#pragma unroll
            for (int j = 0; j < 16; j++) {
                float4 x4 = *(const float4*)(s_c + (g * 16 + j) * CC + cc);
                acc[j] += w4.x * x4.x + w4.y * x4.y + w4.z * x4.z + w4.w * x4.w;
            }
        }
        float bb = outb[o];
#pragma unroll
        for (int j = 0; j < 16; j++) s_a[(g * 16 + j) * CC + o] = acc[j] + bb;
        __syncthreads();
    }

    // ---- LN3 + relu + store ----
    for (int qq = wid; qq < 32; qq += 8) {
        if (q0 + qq >= NQ) continue;
        float4 v = *(const float4*)(s_a + qq * CC + lane * 4);
        float s = v.x + v.y + v.z + v.w;
        float s2 = v.x * v.x + v.y * v.y + v.z * v.z + v.w * v.w;
#pragma unroll
        for (int off = 16; off; off >>= 1) {
            s += __shfl_xor_sync(0xffffffffu, s, off);
            s2 += __shfl_xor_sync(0xffffffffu, s2, off);
        }
        float mean = s * (1.f / 128.f);
        float var = s2 * (1.f / 128.f) - mean * mean;
        float inv = rsqrtf(var + 1e-5f);
        float4 g4 = *(const float4*)(ln3g + lane * 4);
        float4 b4 = *(const float4*)(ln3b + lane * 4);
        v.x = fmaxf((v.x - mean) * inv * g4.x + b4.x, 0.f);
        v.y = fmaxf((v.y - mean) * inv * g4.y + b4.y, 0.f);
        v.z = fmaxf((v.z - mean) * inv * g4.z + b4.z, 0.f);
        v.w = fmaxf((v.w - mean) * inv * g4.w + b4.w, 0.f);
        *(float4*)(out + (size_t)(q0 + qq) * OUTC + lane * 4) = v;
    }
}

// ---------------------------------------------------------------------------
extern "C" void kernel_launch(void* const* d_in, const int* in_sizes, int n_in,
                              void* d_out, int out_size) {
    const float* vf = (const float*)d_in[0];
    const float* coords = (const float*)d_in[1];
    const int* kidx = (const int*)d_in[2];
    const int* kmask = (const int*)d_in[3];
    const float* ipw = (const float*)d_in[4];
    const float* ipb = (const float*)d_in[5];
    const float* wo = (const float*)d_in[6];
    const float* bo = (const float*)d_in[7];
    const float* kpw = (const float*)d_in[8];
    const float* kpb = (const float*)d_in[9];
    const float* ln1g = (const float*)d_in[10];
    const float* ln1b = (const float*)d_in[11];
    const float* ln2g = (const float*)d_in[12];
    const float* ln2b = (const float*)d_in[13];
    const float* f1w = (const float*)d_in[14];
    const float* f1b = (const float*)d_in[15];
    const float* f2w = (const float*)d_in[16];
    const float* f2b = (const float*)d_in[17];
    const float* outw = (const float*)d_in[18];
    const float* outb = (const float*)d_in[19];
    const float* ln3g = (const float*)d_in[20];
    const float* ln3b = (const float*)d_in[21];
    float* out = (float*)d_out;

    cudaFuncSetAttribute(k_qw, cudaFuncAttributeMaxDynamicSharedMemorySize, 65536);
    cudaFuncSetAttribute(k_tail, cudaFuncAttributeMaxDynamicSharedMemorySize, 81920);

    k_qw<<<(NQ + 63) / 64, 256, 65536>>>(vf, ipw, ipb);
    k_attn<<<NQ, 128>>>(vf, coords, kidx, kmask, kpw, kpb, ipw, ipb);
    k_tail<<<(NQ + 31) / 32, 256, 81920>>>(vf, wo, bo, ln1g, ln1b, ln2g, ln2b,
                                           f1w, f1b, f2w, f2b, outw, outb,
                                           ln3g, ln3b, out);
}

// round 11
// speedup vs baseline: 1.4325x; 1.1562x over previous
#include <cuda_runtime.h>
#include <math.h>

#define NQ   50000
#define KK   48
#define CC   128
#define HH   8
#define DD   16
#define FF_  256
#define OUTC 128

// Scratch (device globals: allocation-guard-safe)
__device__ float g_QW[(size_t)NQ * 1024];   // [n][h][c]  = sum_d q[hd]*wk[hd][c]
__device__ float g_QB[(size_t)NQ * 8];      // [n][h]     = sum_d q[hd]*bk[hd]
__device__ float g_mix[(size_t)NQ * 1024];  // [n][h][c]  = sum_k attn[h,k]*kf[k,c]

// ---------------------------------------------------------------------------
// Kernel 1: Q = vf @ wq^T + bq, then QW[n,h,c] = sum_d Q[hd]*wk[hd,c], QB.
// (identical to the 2186us R2 version)
// ---------------------------------------------------------------------------
__global__ __launch_bounds__(256) void k_qw(const float* __restrict__ vf,
                                            const float* __restrict__ ipw,
                                            const float* __restrict__ ipb) {
    extern __shared__ float sm[];
    float* xs = sm;            // 64*128
    float* qs = sm + 64 * 128; // 64*128
    int q0 = blockIdx.x * 64;
    int tid = threadIdx.x;

    for (int i = tid; i < 64 * 128; i += 256) {
        int qq = i >> 7;
        xs[i] = (q0 + qq < NQ) ? vf[(size_t)(q0 + qq) * CC + (i & 127)] : 0.f;
    }
    __syncthreads();

    int o = tid & 127, g = tid >> 7;
    // ---- Q ----
    {
        float acc[32];
#pragma unroll
        for (int j = 0; j < 32; j++) acc[j] = 0.f;
        const float* wq = ipw + (size_t)o * CC;  // wq rows 0..127
        for (int cc = 0; cc < CC; cc += 4) {
            float4 w4 = *(const float4*)(wq + cc);
#pragma unroll
            for (int j = 0; j < 32; j++) {
                float4 x4 = *(const float4*)(xs + (g * 32 + j) * CC + cc);
                acc[j] += w4.x * x4.x + w4.y * x4.y + w4.z * x4.z + w4.w * x4.w;
            }
        }
        float b = ipb[o];
#pragma unroll
        for (int j = 0; j < 32; j++) qs[(g * 32 + j) * CC + o] = acc[j] + b;
    }
    __syncthreads();

    // ---- QW ----
    {
        const int c = o;
        for (int h = 0; h < HH; h++) {
            float wreg[16];
#pragma unroll
            for (int d = 0; d < 16; d++)
                wreg[d] = ipw[(size_t)(CC + h * 16 + d) * CC + c];  // wk rows 128..255
            for (int j = 0; j < 32; j++) {
                int qq = g * 32 + j;
                float a = 0.f;
#pragma unroll
                for (int d4 = 0; d4 < 16; d4 += 4) {
                    float4 q4 = *(const float4*)(qs + qq * CC + h * 16 + d4);
                    a += q4.x * wreg[d4] + q4.y * wreg[d4 + 1] +
                         q4.z * wreg[d4 + 2] + q4.w * wreg[d4 + 3];
                }
                if (q0 + qq < NQ) g_QW[(size_t)(q0 + qq) * 1024 + h * 128 + c] = a;
            }
        }
    }
    // ---- QB ----
    for (int i = tid; i < 64 * 8; i += 256) {
        int qq = i >> 3, h = i & 7;
        if (q0 + qq < NQ) {
            float a = 0.f;
#pragma unroll
            for (int d = 0; d < 16; d++)
                a += qs[qq * CC + h * 16 + d] * ipb[CC + h * 16 + d];
            g_QB[(size_t)(q0 + qq) * 8 + h] = a;
        }
    }
}

// ---------------------------------------------------------------------------
// Kernel 2: per-query attention. Identical to R2 EXCEPT the score stage,
// which uses the SHFL-lean lane map (head = lane>>2, cseg = lane&3):
// 32 FFMA + 2 SHFL per warp-key instead of 32 FFMA + 40 SHFL.
// Writes g_mix (no wv fusion — that was the R9 regression).
// ---------------------------------------------------------------------------
__global__ __launch_bounds__(128) void k_attn(const float* __restrict__ vf,
                                              const float* __restrict__ coords,
                                              const int* __restrict__ kidx,
                                              const int* __restrict__ kmask,
                                              const float* __restrict__ kpw,
                                              const float* __restrict__ kpb) {
    __shared__ float kf[KK][CC];
    __shared__ float s_sc[HH][KK];
    __shared__ int s_idx[KK];
    __shared__ int s_msk[KK];
    __shared__ float s_rel[KK][4];
    __shared__ float s_qc[3];

    int n = blockIdx.x;
    int tid = threadIdx.x;
    if (tid < 3) s_qc[tid] = coords[(size_t)n * 3 + tid];
    if (tid < KK) {
        s_idx[tid] = kidx[(size_t)n * KK + tid];
        s_msk[tid] = kmask[(size_t)n * KK + tid];
    }
    __syncthreads();
    if (tid < KK) {
        int id = s_idx[tid];
        s_rel[tid][0] = coords[(size_t)id * 3 + 0] - s_qc[0];
        s_rel[tid][1] = coords[(size_t)id * 3 + 1] - s_qc[1];
        s_rel[tid][2] = coords[(size_t)id * 3 + 2] - s_qc[2];
    }
    float w0 = kpw[tid * 3 + 0], w1 = kpw[tid * 3 + 1], w2 = kpw[tid * 3 + 2];
    float pb = kpb[tid];
    __syncthreads();

    // gather + pos_emb
#pragma unroll 4
    for (int k = 0; k < KK; k++) {
        float pe = s_rel[k][0] * w0 + s_rel[k][1] * w1 + s_rel[k][2] * w2 + pb;
        pe = fmaxf(pe, 0.f);
        kf[k][tid] = vf[(size_t)s_idx[k] * CC + tid] + pe;
    }

    int lane = tid & 31, wp = tid >> 5;
    // score lane mapping: head = lane>>2, channel segment = lane&3 (32 ch each)
    int hh = lane >> 2, cseg = lane & 3;
    const float* qwb = g_QW + (size_t)n * 1024 + hh * 128 + cseg * 32;
    float4 qp[8];
#pragma unroll
    for (int i = 0; i < 8; i++)
        qp[i] = *(const float4*)(qwb + (((i + 2 * cseg) & 7) << 2));
    float qb = g_QB[(size_t)n * 8 + hh];
    __syncthreads();

    // scores: warp wp handles keys wp, wp+4, ... ; 8 heads in parallel lanes.
    // Per-lane 32-ch dot with a cseg-rotated visit order (conflict-free LDS).
    for (int k = wp; k < KK; k += 4) {
        const float* kr = &kf[k][cseg * 32];
        float s = 0.f;
#pragma unroll
        for (int i = 0; i < 8; i++) {
            float4 k4 = *(const float4*)(kr + (((i + 2 * cseg) & 7) << 2));
            s += qp[i].x * k4.x + qp[i].y * k4.y + qp[i].z * k4.z + qp[i].w * k4.w;
        }
        s += __shfl_xor_sync(0xffffffffu, s, 1);
        s += __shfl_xor_sync(0xffffffffu, s, 2);
        if (cseg == 0) s_sc[hh][k] = (s + qb) * 0.25f;  // 1/sqrt(16)
    }
    __syncthreads();

    // mask + softmax: warp wp handles heads wp and wp+4
    for (int h = wp; h < HH; h += 4) {
        float a = s_sc[h][lane];
        if (s_msk[lane]) a = -1e9f;
        float bsc = -INFINITY;
        if (lane < 16) {
            bsc = s_sc[h][32 + lane];
            if (s_msk[32 + lane]) bsc = -1e9f;
        }
        float m = fmaxf(a, bsc);
#pragma unroll
        for (int off = 16; off; off >>= 1) m = fmaxf(m, __shfl_xor_sync(0xffffffffu, m, off));
        float ea = expf(a - m);
        float eb = (lane < 16) ? expf(bsc - m) : 0.f;
        float s = ea + eb;
#pragma unroll
        for (int off = 16; off; off >>= 1) s += __shfl_xor_sync(0xffffffffu, s, off);
        float inv = 1.f / s;
        s_sc[h][lane] = ea * inv;
        if (lane < 16) s_sc[h][32 + lane] = eb * inv;
    }
    __syncthreads();

    // mix[h][c] = sum_k attn[h,k]*kf[k,c]; warp wp -> heads 2wp, 2wp+1
    int h0 = 2 * wp, h1 = h0 + 1;
    float4 a0 = make_float4(0, 0, 0, 0), a1 = make_float4(0, 0, 0, 0);
#pragma unroll 4
    for (int k = 0; k < KK; k++) {
        float4 k4 = *(const float4*)(&kf[k][lane * 4]);
        float t0 = s_sc[h0][k], t1 = s_sc[h1][k];
        a0.x += k4.x * t0; a0.y += k4.y * t0; a0.z += k4.z * t0; a0.w += k4.w * t0;
        a1.x += k4.x * t1; a1.y += k4.y * t1; a1.z += k4.z * t1; a1.w += k4.w * t1;
    }
    float* mo = g_mix + (size_t)n * 1024;
    *(float4*)(mo + h0 * 128 + lane * 4) = a0;
    *(float4*)(mo + h1 * 128 + lane * 4) = a1;
}

// ---------------------------------------------------------------------------
// LayerNorm over 128 channels for a 32-query smem tile; one warp per query.
// ---------------------------------------------------------------------------
__device__ __forceinline__ void ln_norm(float* buf, const float* __restrict__ gg,
                                        const float* __restrict__ bb, int lane, int wid) {
    for (int qq = wid; qq < 32; qq += 8) {
        float4 v = *(const float4*)(buf + qq * CC + lane * 4);
        float s = v.x + v.y + v.z + v.w;
        float s2 = v.x * v.x + v.y * v.y + v.z * v.z + v.w * v.w;
#pragma unroll
        for (int off = 16; off; off >>= 1) {
            s += __shfl_xor_sync(0xffffffffu, s, off);
            s2 += __shfl_xor_sync(0xffffffffu, s2, off);
        }
        float mean = s * (1.f / 128.f);
        float var = s2 * (1.f / 128.f) - mean * mean;
        float inv = rsqrtf(var + 1e-5f);
        float4 g4 = *(const float4*)(gg + lane * 4);
        float4 b4 = *(const float4*)(bb + lane * 4);
        v.x = (v.x - mean) * inv * g4.x + b4.x;
        v.y = (v.y - mean) * inv * g4.y + b4.y;
        v.z = (v.z - mean) * inv * g4.z + b4.z;
        v.w = (v.w - mean) * inv * g4.w + b4.w;
        *(float4*)(buf + qq * CC + lane * 4) = v;
    }
}

// ---------------------------------------------------------------------------
// Kernel 3: dense tail (identical to the 2186us R2 version, incl. the
// register-blocked wv stage over staged g_mix tiles).
// ---------------------------------------------------------------------------
__global__ __launch_bounds__(256) void k_tail(
    const float* __restrict__ vf, const float* __restrict__ ipw,
    const float* __restrict__ ipb, const float* __restrict__ wo,
    const float* __restrict__ bo, const float* __restrict__ ln1g,
    const float* __restrict__ ln1b, const float* __restrict__ ln2g,
    const float* __restrict__ ln2b, const float* __restrict__ f1w,
    const float* __restrict__ f1b, const float* __restrict__ f2w,
    const float* __restrict__ f2b, const float* __restrict__ outw,
    const float* __restrict__ outb, const float* __restrict__ ln3g,
    const float* __restrict__ ln3b, float* __restrict__ out) {
    extern __shared__ float sm[];
    float* s_a = sm;           // 32*128: mix tile, later pre-LN3 out
    float* s_c = sm + 4096;    // 32*128: ctx, later x2
    float* s_x = sm + 8192;    // 32*128: x1
    float* s_h = sm + 12288;   // 32*256: hidden
    int q0 = blockIdx.x * 32;
    int tid = threadIdx.x;
    int lane = tid & 31, wid = tid >> 5;

    // ---- ctx[qq][h*16+d] = sum_c mix[qq][h][c]*wv[h16+d][c] + bv ----
    {
        int dq = tid & 15, r = tid >> 4;  // r in 0..15
        for (int h = 0; h < HH; h++) {
            __syncthreads();
            for (int i = tid; i < 32 * 128; i += 256) {
                int qq = i >> 7;
                s_a[i] = (q0 + qq < NQ)
                             ? g_mix[(size_t)(q0 + qq) * 1024 + h * 128 + (i & 127)]
                             : 0.f;
            }
            __syncthreads();
            int o = h * 16 + dq;
            const float* wv = ipw + (size_t)(2 * CC + o) * CC;  // wv rows 256..383
            float a0 = 0.f, a1 = 0.f;
            for (int cc = 0; cc < CC; cc += 4) {
                float4 w4 = *(const float4*)(wv + cc);
                float4 m0 = *(const float4*)(s_a + r * CC + cc);
                float4 m1 = *(const float4*)(s_a + (r + 16) * CC + cc);
                a0 += w4.x * m0.x + w4.y * m0.y + w4.z * m0.z + w4.w * m0.w;
                a1 += w4.x * m1.x + w4.y * m1.y + w4.z * m1.z + w4.w * m1.w;
            }
            float bb = ipb[2 * CC + o];
            s_c[r * CC + o] = a0 + bb;
            s_c[(r + 16) * CC + o] = a1 + bb;
        }
        __syncthreads();
    }

    // ---- attend = ctx @ wo^T + bo ; x1 = vf + attend ----
    {
        int c = tid & 127, g = tid >> 7;
        float acc[16];
#pragma unroll
        for (int j = 0; j < 16; j++) acc[j] = 0.f;
        const float* wrow = wo + (size_t)c * CC;
        for (int cc = 0; cc < CC; cc += 4) {
            float4 w4 = *(const float4*)(wrow + cc);
#pragma unroll
            for (int j = 0; j < 16; j++) {
                float4 x4 = *(const float4*)(s_c + (g * 16 + j) * CC + cc);
                acc[j] += w4.x * x4.x + w4.y * x4.y + w4.z * x4.z + w4.w * x4.w;
            }
        }
        float bb = bo[c];
#pragma unroll
        for (int j = 0; j < 16; j++) {
            int qq = g * 16 + j;
            float vfv = (q0 + qq < NQ) ? vf[(size_t)(q0 + qq) * CC + c] : 0.f;
            s_x[qq * CC + c] = vfv + acc[j] + bb;
        }
        __syncthreads();
    }
    ln_norm(s_x, ln1g, ln1b, lane, wid);
    __syncthreads();

    // ---- hidden = relu(x1 @ ff1^T + b1) ----
    {
        int f = tid;
        float acc[32];
#pragma unroll
        for (int j = 0; j < 32; j++) acc[j] = 0.f;
        const float* wrow = f1w + (size_t)f * CC;
        for (int cc = 0; cc < CC; cc += 4) {
            float4 w4 = *(const float4*)(wrow + cc);
#pragma unroll
            for (int j = 0; j < 32; j++) {
                float4 x4 = *(const float4*)(s_x + j * CC + cc);
                acc[j] += w4.x * x4.x + w4.y * x4.y + w4.z * x4.z + w4.w * x4.w;
            }
        }
        float bb = f1b[f];
#pragma unroll
        for (int j = 0; j < 32; j++) s_h[j * FF_ + f] = fmaxf(acc[j] + bb, 0.f);
        __syncthreads();
    }

    // ---- y = hidden @ ff2^T + b2 ; x2 = x1 + y ----
    {
        int c = tid & 127, g = tid >> 7;
        float acc[16];
#pragma unroll
        for (int j = 0; j < 16; j++) acc[j] = 0.f;
        const float* wrow = f2w + (size_t)c * FF_;
        for (int ff = 0; ff < FF_; ff += 4) {
            float4 w4 = *(const float4*)(wrow + ff);
#pragma unroll
            for (int j = 0; j < 16; j++) {
                float4 h4 = *(const float4*)(s_h + (g * 16 + j) * FF_ + ff);
                acc[j] += w4.x * h4.x + w4.y * h4.y + w4.z * h4.z + w4.w * h4.w;
            }
        }
        float bb = f2b[c];
#pragma unroll
        for (int j = 0; j < 16; j++) {
            int qq = g * 16 + j;
            s_c[qq * CC + c] = s_x[qq * CC + c] + acc[j] + bb;
        }
        __syncthreads();
    }
    ln_norm(s_c, ln2g, ln2b, lane, wid);
    __syncthreads();

    // ---- o = x2 @ outw^T + outb ----
    {
        int o = tid & 127, g = tid >> 7;
        float acc[16];
#pragma unroll
        for (int j = 0; j < 16; j++) acc[j] = 0.f;
        const float* wrow = outw + (size_t)o * CC;
        for (int cc = 0; cc < CC; cc += 4) {
            float4 w4 = *(const float4*)(wrow + cc);
#pragma unroll
            for (int j = 0; j < 16; j++) {
                float4 x4 = *(const float4*)(s_c + (g * 16 + j) * CC + cc);
                acc[j] += w4.x * x4.x + w4.y * x4.y + w4.z * x4.z + w4.w * x4.w;
            }
        }
        float bb = outb[o];
#pragma unroll
        for (int j = 0; j < 16; j++) s_a[(g * 16 + j) * CC + o] = acc[j] + bb;
        __syncthreads();
    }

    // ---- LN3 + relu + store ----
    for (int qq = wid; qq < 32; qq += 8) {
        if (q0 + qq >= NQ) continue;
        float4 v = *(const float4*)(s_a + qq * CC + lane * 4);
        float s = v.x + v.y + v.z + v.w;
        float s2 = v.x * v.x + v.y * v.y + v.z * v.z + v.w * v.w;
#pragma unroll
        for (int off = 16; off; off >>= 1) {
            s += __shfl_xor_sync(0xffffffffu, s, off);
            s2 += __shfl_xor_sync(0xffffffffu, s2, off);
        }
        float mean = s * (1.f / 128.f);
        float var = s2 * (1.f / 128.f) - mean * mean;
        float inv = rsqrtf(var + 1e-5f);
        float4 g4 = *(const float4*)(ln3g + lane * 4);
        float4 b4 = *(const float4*)(ln3b + lane * 4);
        v.x = fmaxf((v.x - mean) * inv * g4.x + b4.x, 0.f);
        v.y = fmaxf((v.y - mean) * inv * g4.y + b4.y, 0.f);
        v.z = fmaxf((v.z - mean) * inv * g4.z + b4.z, 0.f);
        v.w = fmaxf((v.w - mean) * inv * g4.w + b4.w, 0.f);
        *(float4*)(out + (size_t)(q0 + qq) * OUTC + lane * 4) = v;
    }
}

// ---------------------------------------------------------------------------
extern "C" void kernel_launch(void* const* d_in, const int* in_sizes, int n_in,
                              void* d_out, int out_size) {
    const float* vf = (const float*)d_in[0];
    const float* coords = (const float*)d_in[1];
    const int* kidx = (const int*)d_in[2];
    const int* kmask = (const int*)d_in[3];
    const float* ipw = (const float*)d_in[4];
    const float* ipb = (const float*)d_in[5];
    const float* wo = (const float*)d_in[6];
    const float* bo = (const float*)d_in[7];
    const float* kpw = (const float*)d_in[8];
    const float* kpb = (const float*)d_in[9];
    const float* ln1g = (const float*)d_in[10];
    const float* ln1b = (const float*)d_in[11];
    const float* ln2g = (const float*)d_in[12];
    const float* ln2b = (const float*)d_in[13];
    const float* f1w = (const float*)d_in[14];
    const float* f1b = (const float*)d_in[15];
    const float* f2w = (const float*)d_in[16];
    const float* f2b = (const float*)d_in[17];
    const float* outw = (const float*)d_in[18];
    const float* outb = (const float*)d_in[19];
    const float* ln3g = (const float*)d_in[20];
    const float* ln3b = (const float*)d_in[21];
    float* out = (float*)d_out;

    cudaFuncSetAttribute(k_qw, cudaFuncAttributeMaxDynamicSharedMemorySize, 65536);
    cudaFuncSetAttribute(k_tail, cudaFuncAttributeMaxDynamicSharedMemorySize, 81920);

    k_qw<<<(NQ + 63) / 64, 256, 65536>>>(vf, ipw, ipb);
    k_attn<<<NQ, 128>>>(vf, coords, kidx, kmask, kpw, kpb);
    k_tail<<<(NQ + 31) / 32, 256, 81920>>>(vf, ipw, ipb, wo, bo, ln1g, ln1b,
                                           ln2g, ln2b, f1w, f1b, f2w, f2b,
                                           outw, outb, ln3g, ln3b, out);
}

// round 17
// speedup vs baseline: 1.7627x; 1.2305x over previous
#include <cuda_runtime.h>
#include <math.h>

#define NQ   50000
#define KK   48
#define CC   128
#define HH   8
#define DD   16
#define FF_  256
#define OUTC 128

// Scratch (device globals: allocation-guard-safe)
__device__ float g_QW[(size_t)NQ * 1024];   // [n][h][c]  = sum_d q[hd]*wk[hd][c]
__device__ float g_QB[(size_t)NQ * 8];      // [n][h]     = sum_d q[hd]*bk[hd]
__device__ float g_mix[(size_t)NQ * 1024];  // [n][h][c]  = sum_k attn[h,k]*kf[k,c]

// Transposed weights (column-major: [in_ch][out_ch]) for coalesced lane loads
#define OFF_WQ  0
#define OFF_WV  16384
#define OFF_WO  32768
#define OFF_F1  49152   // [cc][f]  128x256
#define OFF_F2  81920   // [ff][c]  256x128
#define OFF_OUT 114688
__device__ float g_wT[131072];

// ---------------------------------------------------------------------------
// Kernel 0: transpose the 6 weight matrices into g_wT. Tiny (<10us).
// ---------------------------------------------------------------------------
__global__ void k_tr(const float* __restrict__ ipw, const float* __restrict__ wo,
                     const float* __restrict__ f1w, const float* __restrict__ f2w,
                     const float* __restrict__ outw) {
    __shared__ float t[32][33];
    int m = blockIdx.z;
    const float* src; float* dst; int R, C;
    switch (m) {
        case 0: src = ipw;             dst = g_wT + OFF_WQ;  R = 128; C = 128; break;
        case 1: src = ipw + 256 * 128; dst = g_wT + OFF_WV;  R = 128; C = 128; break;
        case 2: src = wo;              dst = g_wT + OFF_WO;  R = 128; C = 128; break;
        case 3: src = f1w;             dst = g_wT + OFF_F1;  R = 256; C = 128; break;
        case 4: src = f2w;             dst = g_wT + OFF_F2;  R = 128; C = 256; break;
        default: src = outw;           dst = g_wT + OFF_OUT; R = 128; C = 128; break;
    }
    int bx = blockIdx.x * 32, by = blockIdx.y * 32;
    if (bx >= C || by >= R) return;
    int x = bx + threadIdx.x;
    for (int i = threadIdx.y; i < 32; i += 8) {
        int y = by + i;
        if (y < R && x < C) t[i][threadIdx.x] = src[y * C + x];
    }
    __syncthreads();
    int xo = by + threadIdx.x;  // dst col = src row
    for (int i = threadIdx.y; i < 32; i += 8) {
        int yo = bx + i;        // dst row = src col
        if (yo < C && xo < R) dst[yo * R + xo] = t[threadIdx.x][i];
    }
}

// ---------------------------------------------------------------------------
// Kernel 1: Q = vf @ wq^T + bq (coalesced wqT loads), then QW, QB.
// ---------------------------------------------------------------------------
__global__ __launch_bounds__(256) void k_qw(const float* __restrict__ vf,
                                            const float* __restrict__ ipw,
                                            const float* __restrict__ ipb) {
    extern __shared__ float sm[];
    float* xs = sm;            // 64*128
    float* qs = sm + 64 * 128; // 64*128
    int q0 = blockIdx.x * 64;
    int tid = threadIdx.x;

    for (int i = tid; i < 64 * 128; i += 256) {
        int qq = i >> 7;
        xs[i] = (q0 + qq < NQ) ? vf[(size_t)(q0 + qq) * CC + (i & 127)] : 0.f;
    }
    __syncthreads();

    int o = tid & 127, g = tid >> 7;
    // ---- Q (coalesced transposed weight loads) ----
    {
        float acc[32];
#pragma unroll
        for (int j = 0; j < 32; j++) acc[j] = 0.f;
        const float* wqT = g_wT + OFF_WQ;  // [cc][o]
        for (int cc = 0; cc < CC; cc += 4) {
            float w0 = wqT[(cc + 0) * CC + o];
            float w1 = wqT[(cc + 1) * CC + o];
            float w2 = wqT[(cc + 2) * CC + o];
            float w3 = wqT[(cc + 3) * CC + o];
#pragma unroll
            for (int j = 0; j < 32; j++) {
                float4 x4 = *(const float4*)(xs + (g * 32 + j) * CC + cc);
                acc[j] += w0 * x4.x + w1 * x4.y + w2 * x4.z + w3 * x4.w;
            }
        }
        float b = ipb[o];
#pragma unroll
        for (int j = 0; j < 32; j++) qs[(g * 32 + j) * CC + o] = acc[j] + b;
    }
    __syncthreads();

    // ---- QW (ipw column reads: already coalesced across c) ----
    {
        const int c = o;
        for (int h = 0; h < HH; h++) {
            float wreg[16];
#pragma unroll
            for (int d = 0; d < 16; d++)
                wreg[d] = ipw[(size_t)(CC + h * 16 + d) * CC + c];  // wk rows 128..255
            for (int j = 0; j < 32; j++) {
                int qq = g * 32 + j;
                float a = 0.f;
#pragma unroll
                for (int d4 = 0; d4 < 16; d4 += 4) {
                    float4 q4 = *(const float4*)(qs + qq * CC + h * 16 + d4);
                    a += q4.x * wreg[d4] + q4.y * wreg[d4 + 1] +
                         q4.z * wreg[d4 + 2] + q4.w * wreg[d4 + 3];
                }
                if (q0 + qq < NQ) g_QW[(size_t)(q0 + qq) * 1024 + h * 128 + c] = a;
            }
        }
    }
    // ---- QB ----
    for (int i = tid; i < 64 * 8; i += 256) {
        int qq = i >> 3, h = i & 7;
        if (q0 + qq < NQ) {
            float a = 0.f;
#pragma unroll
            for (int d = 0; d < 16; d++)
                a += qs[qq * CC + h * 16 + d] * ipb[CC + h * 16 + d];
            g_QB[(size_t)(q0 + qq) * 8 + h] = a;
        }
    }
}

// ---------------------------------------------------------------------------
// Kernel 2: per-query attention (identical to the 2099us R11 version).
// ---------------------------------------------------------------------------
__global__ __launch_bounds__(128) void k_attn(const float* __restrict__ vf,
                                              const float* __restrict__ coords,
                                              const int* __restrict__ kidx,
                                              const int* __restrict__ kmask,
                                              const float* __restrict__ kpw,
                                              const float* __restrict__ kpb) {
    __shared__ float kf[KK][CC];
    __shared__ float s_sc[HH][KK];
    __shared__ int s_idx[KK];
    __shared__ int s_msk[KK];
    __shared__ float s_rel[KK][4];
    __shared__ float s_qc[3];

    int n = blockIdx.x;
    int tid = threadIdx.x;
    if (tid < 3) s_qc[tid] = coords[(size_t)n * 3 + tid];
    if (tid < KK) {
        s_idx[tid] = kidx[(size_t)n * KK + tid];
        s_msk[tid] = kmask[(size_t)n * KK + tid];
    }
    __syncthreads();
    if (tid < KK) {
        int id = s_idx[tid];
        s_rel[tid][0] = coords[(size_t)id * 3 + 0] - s_qc[0];
        s_rel[tid][1] = coords[(size_t)id * 3 + 1] - s_qc[1];
        s_rel[tid][2] = coords[(size_t)id * 3 + 2] - s_qc[2];
    }
    float w0 = kpw[tid * 3 + 0], w1 = kpw[tid * 3 + 1], w2 = kpw[tid * 3 + 2];
    float pb = kpb[tid];
    __syncthreads();

#pragma unroll 4
    for (int k = 0; k < KK; k++) {
        float pe = s_rel[k][0] * w0 + s_rel[k][1] * w1 + s_rel[k][2] * w2 + pb;
        pe = fmaxf(pe, 0.f);
        kf[k][tid] = vf[(size_t)s_idx[k] * CC + tid] + pe;
    }

    int lane = tid & 31, wp = tid >> 5;
    int hh = lane >> 2, cseg = lane & 3;
    const float* qwb = g_QW + (size_t)n * 1024 + hh * 128 + cseg * 32;
    float4 qp[8];
#pragma unroll
    for (int i = 0; i < 8; i++)
        qp[i] = *(const float4*)(qwb + (((i + 2 * cseg) & 7) << 2));
    float qb = g_QB[(size_t)n * 8 + hh];
    __syncthreads();

    for (int k = wp; k < KK; k += 4) {
        const float* kr = &kf[k][cseg * 32];
        float s = 0.f;
#pragma unroll
        for (int i = 0; i < 8; i++) {
            float4 k4 = *(const float4*)(kr + (((i + 2 * cseg) & 7) << 2));
            s += qp[i].x * k4.x + qp[i].y * k4.y + qp[i].z * k4.z + qp[i].w * k4.w;
        }
        s += __shfl_xor_sync(0xffffffffu, s, 1);
        s += __shfl_xor_sync(0xffffffffu, s, 2);
        if (cseg == 0) s_sc[hh][k] = (s + qb) * 0.25f;  // 1/sqrt(16)
    }
    __syncthreads();

    for (int h = wp; h < HH; h += 4) {
        float a = s_sc[h][lane];
        if (s_msk[lane]) a = -1e9f;
        float bsc = -INFINITY;
        if (lane < 16) {
            bsc = s_sc[h][32 + lane];
            if (s_msk[32 + lane]) bsc = -1e9f;
        }
        float m = fmaxf(a, bsc);
#pragma unroll
        for (int off = 16; off; off >>= 1) m = fmaxf(m, __shfl_xor_sync(0xffffffffu, m, off));
        float ea = expf(a - m);
        float eb = (lane < 16) ? expf(bsc - m) : 0.f;
        float s = ea + eb;
#pragma unroll
        for (int off = 16; off; off >>= 1) s += __shfl_xor_sync(0xffffffffu, s, off);
        float inv = 1.f / s;
        s_sc[h][lane] = ea * inv;
        if (lane < 16) s_sc[h][32 + lane] = eb * inv;
    }
    __syncthreads();

    int h0 = 2 * wp, h1 = h0 + 1;
    float4 a0 = make_float4(0, 0, 0, 0), a1 = make_float4(0, 0, 0, 0);
#pragma unroll 4
    for (int k = 0; k < KK; k++) {
        float4 k4 = *(const float4*)(&kf[k][lane * 4]);
        float t0 = s_sc[h0][k], t1 = s_sc[h1][k];
        a0.x += k4.x * t0; a0.y += k4.y * t0; a0.z += k4.z * t0; a0.w += k4.w * t0;
        a1.x += k4.x * t1; a1.y += k4.y * t1; a1.z += k4.z * t1; a1.w += k4.w * t1;
    }
    float* mo = g_mix + (size_t)n * 1024;
    *(float4*)(mo + h0 * 128 + lane * 4) = a0;
    *(float4*)(mo + h1 * 128 + lane * 4) = a1;
}

// ---------------------------------------------------------------------------
// LayerNorm over 128 channels for a 32-query smem tile; one warp per query.
// ---------------------------------------------------------------------------
__device__ __forceinline__ void ln_norm(float* buf, const float* __restrict__ gg,
                                        const float* __restrict__ bb, int lane, int wid) {
    for (int qq = wid; qq < 32; qq += 8) {
        float4 v = *(const float4*)(buf + qq * CC + lane * 4);
        float s = v.x + v.y + v.z + v.w;
        float s2 = v.x * v.x + v.y * v.y + v.z * v.z + v.w * v.w;
#pragma unroll
        for (int off = 16; off; off >>= 1) {
            s += __shfl_xor_sync(0xffffffffu, s, off);
            s2 += __shfl_xor_sync(0xffffffffu, s2, off);
        }
        float mean = s * (1.f / 128.f);
        float var = s2 * (1.f / 128.f) - mean * mean;
        float inv = rsqrtf(var + 1e-5f);
        float4 g4 = *(const float4*)(gg + lane * 4);
        float4 b4 = *(const float4*)(bb + lane * 4);
        v.x = (v.x - mean) * inv * g4.x + b4.x;
        v.y = (v.y - mean) * inv * g4.y + b4.y;
        v.z = (v.z - mean) * inv * g4.z + b4.z;
        v.w = (v.w - mean) * inv * g4.w + b4.w;
        *(float4*)(buf + qq * CC + lane * 4) = v;
    }
}

// ---------------------------------------------------------------------------
// Kernel 3: dense tail — same structure as R2/R11, but ALL weight loads go
// through the transposed copies (coalesced: 1 wavefront instead of 16-32).
// ---------------------------------------------------------------------------
__global__ __launch_bounds__(256) void k_tail(
    const float* __restrict__ vf, const float* __restrict__ ipb,
    const float* __restrict__ bo, const float* __restrict__ ln1g,
    const float* __restrict__ ln1b, const float* __restrict__ ln2g,
    const float* __restrict__ ln2b, const float* __restrict__ f1b,
    const float* __restrict__ f2b, const float* __restrict__ outb,
    const float* __restrict__ ln3g, const float* __restrict__ ln3b,
    float* __restrict__ out) {
    extern __shared__ float sm[];
    float* s_a = sm;           // 32*128: mix tile, later pre-LN3 out
    float* s_c = sm + 4096;    // 32*128: ctx, later x2
    float* s_x = sm + 8192;    // 32*128: x1
    float* s_h = sm + 12288;   // 32*256: hidden
    int q0 = blockIdx.x * 32;
    int tid = threadIdx.x;
    int lane = tid & 31, wid = tid >> 5;

    // ---- ctx[qq][h*16+d] = sum_c mix[qq][h][c]*wv[h16+d][c] + bv ----
    {
        int dq = tid & 15, r = tid >> 4;  // r in 0..15
        const float* wvT = g_wT + OFF_WV;  // [cc][o]
        for (int h = 0; h < HH; h++) {
            __syncthreads();
            for (int i = tid; i < 32 * 128; i += 256) {
                int qq = i >> 7;
                s_a[i] = (q0 + qq < NQ)
                             ? g_mix[(size_t)(q0 + qq) * 1024 + h * 128 + (i & 127)]
                             : 0.f;
            }
            __syncthreads();
            int o = h * 16 + dq;
            float a0 = 0.f, a1 = 0.f;
            for (int cc = 0; cc < CC; cc += 4) {
                float w0 = wvT[(cc + 0) * CC + o];
                float w1 = wvT[(cc + 1) * CC + o];
                float w2 = wvT[(cc + 2) * CC + o];
                float w3 = wvT[(cc + 3) * CC + o];
                float4 m0 = *(const float4*)(s_a + r * CC + cc);
                float4 m1 = *(const float4*)(s_a + (r + 16) * CC + cc);
                a0 += w0 * m0.x + w1 * m0.y + w2 * m0.z + w3 * m0.w;
                a1 += w0 * m1.x + w1 * m1.y + w2 * m1.z + w3 * m1.w;
            }
            float bb = ipb[2 * CC + o];
            s_c[r * CC + o] = a0 + bb;
            s_c[(r + 16) * CC + o] = a1 + bb;
        }
        __syncthreads();
    }

    // ---- attend = ctx @ wo^T + bo ; x1 = vf + attend ----
    {
        int c = tid & 127, g = tid >> 7;
        float acc[16];
#pragma unroll
        for (int j = 0; j < 16; j++) acc[j] = 0.f;
        const float* woT = g_wT + OFF_WO;  // [cc][c]
        for (int cc = 0; cc < CC; cc += 4) {
            float w0 = woT[(cc + 0) * CC + c];
            float w1 = woT[(cc + 1) * CC + c];
            float w2 = woT[(cc + 2) * CC + c];
            float w3 = woT[(cc + 3) * CC + c];
#pragma unroll
            for (int j = 0; j < 16; j++) {
                float4 x4 = *(const float4*)(s_c + (g * 16 + j) * CC + cc);
                acc[j] += w0 * x4.x + w1 * x4.y + w2 * x4.z + w3 * x4.w;
            }
        }
        float bb = bo[c];
#pragma unroll
        for (int j = 0; j < 16; j++) {
            int qq = g * 16 + j;
            float vfv = (q0 + qq < NQ) ? vf[(size_t)(q0 + qq) * CC + c] : 0.f;
            s_x[qq * CC + c] = vfv + acc[j] + bb;
        }
        __syncthreads();
    }
    ln_norm(s_x, ln1g, ln1b, lane, wid);
    __syncthreads();

    // ---- hidden = relu(x1 @ ff1^T + b1) ----
    {
        int f = tid;
        float acc[32];
#pragma unroll
        for (int j = 0; j < 32; j++) acc[j] = 0.f;
        const float* f1T = g_wT + OFF_F1;  // [cc][f], stride 256
        for (int cc = 0; cc < CC; cc += 4) {
            float w0 = f1T[(cc + 0) * FF_ + f];
            float w1 = f1T[(cc + 1) * FF_ + f];
            float w2 = f1T[(cc + 2) * FF_ + f];
            float w3 = f1T[(cc + 3) * FF_ + f];
#pragma unroll
            for (int j = 0; j < 32; j++) {
                float4 x4 = *(const float4*)(s_x + j * CC + cc);
                acc[j] += w0 * x4.x + w1 * x4.y + w2 * x4.z + w3 * x4.w;
            }
        }
        float bb = f1b[f];
#pragma unroll
        for (int j = 0; j < 32; j++) s_h[j * FF_ + f] = fmaxf(acc[j] + bb, 0.f);
        __syncthreads();
    }

    // ---- y = hidden @ ff2^T + b2 ; x2 = x1 + y ----
    {
        int c = tid & 127, g = tid >> 7;
        float acc[16];
#pragma unroll
        for (int j = 0; j < 16; j++) acc[j] = 0.f;
        const float* f2T = g_wT + OFF_F2;  // [ff][c], stride 128
        for (int ff = 0; ff < FF_; ff += 4) {
            float w0 = f2T[(ff + 0) * CC + c];
            float w1 = f2T[(ff + 1) * CC + c];
            float w2 = f2T[(ff + 2) * CC + c];
            float w3 = f2T[(ff + 3) * CC + c];
#pragma unroll
            for (int j = 0; j < 16; j++) {
                float4 h4 = *(const float4*)(s_h + (g * 16 + j) * FF_ + ff);
                acc[j] += w0 * h4.x + w1 * h4.y + w2 * h4.z + w3 * h4.w;
            }
        }
        float bb = f2b[c];
#pragma unroll
        for (int j = 0; j < 16; j++) {
            int qq = g * 16 + j;
            s_c[qq * CC + c] = s_x[qq * CC + c] + acc[j] + bb;
        }
        __syncthreads();
    }
    ln_norm(s_c, ln2g, ln2b, lane, wid);
    __syncthreads();

    // ---- o = x2 @ outw^T + outb ----
    {
        int o = tid & 127, g = tid >> 7;
        float acc[16];
#pragma unroll
        for (int j = 0; j < 16; j++) acc[j] = 0.f;
        const float* outT = g_wT + OFF_OUT;  // [cc][o]
        for (int cc = 0; cc < CC; cc += 4) {
            float w0 = outT[(cc + 0) * CC + o];
            float w1 = outT[(cc + 1) * CC + o];
            float w2 = outT[(cc + 2) * CC + o];
            float w3 = outT[(cc + 3) * CC + o];
#pragma unroll
            for (int j = 0; j < 16; j++) {
                float4 x4 = *(const float4*)(s_c + (g * 16 + j) * CC + cc);
                acc[j] += w0 * x4.x + w1 * x4.y + w2 * x4.z + w3 * x4.w;
            }
        }
        float bb = outb[o];
#pragma unroll
        for (int j = 0; j < 16; j++) s_a[(g * 16 + j) * CC + o] = acc[j] + bb;
        __syncthreads();
    }

    // ---- LN3 + relu + store ----
    for (int qq = wid; qq < 32; qq += 8) {
        if (q0 + qq >= NQ) continue;
        float4 v = *(const float4*)(s_a + qq * CC + lane * 4);
        float s = v.x + v.y + v.z + v.w;
        float s2 = v.x * v.x + v.y * v.y + v.z * v.z + v.w * v.w;
#pragma unroll
        for (int off = 16; off; off >>= 1) {
            s += __shfl_xor_sync(0xffffffffu, s, off);
            s2 += __shfl_xor_sync(0xffffffffu, s2, off);
        }
        float mean = s * (1.f / 128.f);
        float var = s2 * (1.f / 128.f) - mean * mean;
        float inv = rsqrtf(var + 1e-5f);
        float4 g4 = *(const float4*)(ln3g + lane * 4);
        float4 b4 = *(const float4*)(ln3b + lane * 4);
        v.x = fmaxf((v.x - mean) * inv * g4.x + b4.x, 0.f);
        v.y = fmaxf((v.y - mean) * inv * g4.y + b4.y, 0.f);
        v.z = fmaxf((v.z - mean) * inv * g4.z + b4.z, 0.f);
        v.w = fmaxf((v.w - mean) * inv * g4.w + b4.w, 0.f);
        *(float4*)(out + (size_t)(q0 + qq) * OUTC + lane * 4) = v;
    }
}

// ---------------------------------------------------------------------------
extern "C" void kernel_launch(void* const* d_in, const int* in_sizes, int n_in,
                              void* d_out, int out_size) {
    const float* vf = (const float*)d_in[0];
    const float* coords = (const float*)d_in[1];
    const int* kidx = (const int*)d_in[2];
    const int* kmask = (const int*)d_in[3];
    const float* ipw = (const float*)d_in[4];
    const float* ipb = (const float*)d_in[5];
    const float* wo = (const float*)d_in[6];
    const float* bo = (const float*)d_in[7];
    const float* kpw = (const float*)d_in[8];
    const float* kpb = (const float*)d_in[9];
    const float* ln1g = (const float*)d_in[10];
    const float* ln1b = (const float*)d_in[11];
    const float* ln2g = (const float*)d_in[12];
    const float* ln2b = (const float*)d_in[13];
    const float* f1w = (const float*)d_in[14];
    const float* f1b = (const float*)d_in[15];
    const float* f2w = (const float*)d_in[16];
    const float* f2b = (const float*)d_in[17];
    const float* outw = (const float*)d_in[18];
    const float* outb = (const float*)d_in[19];
    const float* ln3g = (const float*)d_in[20];
    const float* ln3b = (const float*)d_in[21];
    float* out = (float*)d_out;

    cudaFuncSetAttribute(k_qw, cudaFuncAttributeMaxDynamicSharedMemorySize, 65536);
    cudaFuncSetAttribute(k_tail, cudaFuncAttributeMaxDynamicSharedMemorySize, 81920);

    dim3 trb(32, 8);
    k_tr<<<dim3(8, 8, 6), trb>>>(ipw, wo, f1w, f2w, outw);
    k_qw<<<(NQ + 63) / 64, 256, 65536>>>(vf, ipw, ipb);
    k_attn<<<NQ, 128>>>(vf, coords, kidx, kmask, kpw, kpb);
    k_tail<<<(NQ + 31) / 32, 256, 81920>>>(vf, ipb, bo, ln1g, ln1b, ln2g, ln2b,
                                           f1b, f2b, outb, ln3g, ln3b, out);
}